// round 15
// baseline (speedup 1.0000x reference)
#include <cuda_runtime.h>
#include <cuda_fp16.h>
#include <math.h>
#include <stdint.h>

// ---------------------------------------------------------------------------
// Problem constants (LlamaAttention: B=2,S=1024,P=1024,E=2048,H=32,KV=8,HD=64)
// ---------------------------------------------------------------------------
constexpr int B_   = 2;
constexpr int S_   = 1024;
constexpr int P_   = 1024;
constexpr int E_   = 2048;
constexpr int H_   = 32;
constexpr int KV_  = 8;
constexpr int HD_  = 64;
constexpr int G_   = H_ / KV_;        // 4
constexpr int CTX_ = P_ + S_;         // 2048
constexpr int M_   = B_ * S_;         // 2048 rows of tokens

// ---------------------------------------------------------------------------
// Scratch (static device allocations are the sanctioned workaround)
// ---------------------------------------------------------------------------
__device__ float    g_Q[(size_t)M_ * E_];                   // fp32 Q (pre-rope)
__device__ float    g_K[(size_t)M_ * KV_ * HD_];            // fp32 new K (pre-rope)
__device__ float    g_V[(size_t)M_ * KV_ * HD_];            // fp32 new V
__device__ uint32_t g_X16[(size_t)M_ * E_ / 2];             // x fp16 plane
__device__ uint32_t g_A16[(size_t)M_ * E_ / 2];             // attn out fp16 plane
__device__ uint32_t g_Wq16[(size_t)E_ * E_ / 2];            // fp16 packed weights
__device__ uint32_t g_Wk16[(size_t)KV_ * HD_ * E_ / 2];
__device__ uint32_t g_Wv16[(size_t)KV_ * HD_ * E_ / 2];
__device__ uint32_t g_Wo16[(size_t)E_ * E_ / 2];
__device__ uint32_t g_Q16[(size_t)M_ * H_ * 32];            // Q fp16 (pre-scaled by log2e/8)
__device__ uint32_t g_K16[(size_t)B_ * KV_ * CTX_ * 32];    // K fp16 [b][kv][t][hd/2]
__device__ uint32_t g_Vt16[(size_t)B_ * KV_ * HD_ * (CTX_/2)]; // V^T fp16 [b][kv][hd][t/2]

// ---------------------------------------------------------------------------
// helpers
// ---------------------------------------------------------------------------
__device__ __forceinline__ uint32_t h2pack(float a, float b)
{
    __half2 h = __floats2half2_rn(a, b);
    return *reinterpret_cast<uint32_t*>(&h);
}

__device__ __forceinline__ float ex2(float x)
{
    float y;
    asm("ex2.approx.f32 %0, %1;" : "=f"(y) : "f"(x));
    return y;
}

__device__ __forceinline__ void mma_f16(float c[4],
    uint32_t a0, uint32_t a1, uint32_t a2, uint32_t a3,
    uint32_t b0, uint32_t b1)
{
    asm volatile(
        "mma.sync.aligned.m16n8k16.row.col.f32.f16.f16.f32 "
        "{%0,%1,%2,%3}, {%4,%5,%6,%7}, {%8,%9}, {%0,%1,%2,%3};"
        : "+f"(c[0]), "+f"(c[1]), "+f"(c[2]), "+f"(c[3])
        : "r"(a0), "r"(a1), "r"(a2), "r"(a3), "r"(b0), "r"(b1));
}

__device__ __forceinline__ void cp16(void* smem_dst, const void* gsrc)
{
    uint32_t d = (uint32_t)__cvta_generic_to_shared(smem_dst);
    asm volatile("cp.async.cg.shared.global [%0], [%1], 16;" :: "r"(d), "l"(gsrc));
}

__device__ __forceinline__ uint32_t sm_addr(const void* p)
{
    return (uint32_t)__cvta_generic_to_shared(p);
}

__device__ __forceinline__ void ldsm4(uint32_t& r0, uint32_t& r1,
                                      uint32_t& r2, uint32_t& r3, uint32_t addr)
{
    asm volatile("ldmatrix.sync.aligned.m8n8.x4.shared.b16 {%0,%1,%2,%3}, [%4];"
                 : "=r"(r0), "=r"(r1), "=r"(r2), "=r"(r3) : "r"(addr));
}

// ---------------------------------------------------------------------------
// prep_all: single launch converting x and all weights to fp16 planes.
// ---------------------------------------------------------------------------
__global__ void prep_all(const float* __restrict__ x,
                         const float* __restrict__ Wq, const float* __restrict__ Wk,
                         const float* __restrict__ Wv, const float* __restrict__ Wo)
{
    const int i = blockIdx.x * blockDim.x + threadIdx.x;
    const int y = blockIdx.y;
    if (y == 0) {
        float2 f = *(const float2*)(x + 2 * i);
        g_X16[i] = h2pack(f.x, f.y);
    } else if (y == 1) {
        float2 f = *(const float2*)(Wq + 2 * i);
        g_Wq16[i] = h2pack(f.x, f.y);
    } else if (y == 2) {
        if (i < KV_ * HD_ * E_ / 2) {
            float2 f = *(const float2*)(Wk + 2 * i);
            g_Wk16[i] = h2pack(f.x, f.y);
        }
    } else if (y == 3) {
        if (i < KV_ * HD_ * E_ / 2) {
            float2 f = *(const float2*)(Wv + 2 * i);
            g_Wv16[i] = h2pack(f.x, f.y);
        }
    } else {
        float2 f = *(const float2*)(Wo + 2 * i);
        g_Wo16[i] = h2pack(f.x, f.y);
    }
}

// ---------------------------------------------------------------------------
// Plain fp16 GEMM core, BK=64 (halved barrier count vs BK=32).
// 128x128 tile, 256 threads, 8 warps (2x4), warp tile 64x32.
// 3-stage cp.async pipeline, ONE __syncthreads per stage, ldmatrix frags.
// ---------------------------------------------------------------------------
constexpr int GSTR3 = 36;             // plane stride in uint32 (32 used + 4 pad)
constexpr int PST3  = 128 * GSTR3;    // uint32 per plane stage (18432 B)
constexpr int GSM3  = 3 * 2 * PST3 * 4;   // 110592 B

__device__ __forceinline__ void gemm3_stage(
    const uint32_t* __restrict__ A, const uint32_t* __restrict__ Bh,
    int Kp, int bm, int bn, int kp0, uint32_t* Ad, uint32_t* Bd, int tid)
{
#pragma unroll
    for (int i = 0; i < 4; i++) {
        int c = tid * 4 + i;                 // 0..1023
        int row = c >> 3, off = (c & 7) * 4;
        cp16(Ad + row * GSTR3 + off, A  + (size_t)(bm + row) * Kp + kp0 + off);
        cp16(Bd + row * GSTR3 + off, Bh + (size_t)(bn + row) * Kp + kp0 + off);
    }
    asm volatile("cp.async.commit_group;" ::: "memory");
}

__device__ __forceinline__ void gemm3_core(
    const uint32_t* __restrict__ A, const uint32_t* __restrict__ Bh,
    float* __restrict__ C, int N, int K, int bm, int bn, char* smraw)
{
    uint32_t* As = (uint32_t*)smraw;
    uint32_t* Bs = (uint32_t*)(smraw + 3 * PST3 * 4);
    const int tid  = threadIdx.x;
    const int warp = tid >> 5;
    const int lane = tid & 31;
    const int g    = lane >> 2;
    const int tg   = lane & 3;
    const int wm   = (warp >> 2) * 64;
    const int wn   = (warp & 3) * 32;
    const int Kp   = K / 2;

    const int lA_row = (lane & 7) + ((lane >> 3) & 1) * 8;
    const int lA_col = ((lane >> 4) & 1) * 4;
    const int lB_row = (lane & 7) + ((lane >> 4) & 1) * 8;
    const int lB_col = ((lane >> 3) & 1) * 4;

    float acc[4][4][4];
#pragma unroll
    for (int i = 0; i < 4; i++)
#pragma unroll
        for (int j = 0; j < 4; j++)
#pragma unroll
            for (int r = 0; r < 4; r++) acc[i][j][r] = 0.f;

    const int nst = K / 64;    // 32
    gemm3_stage(A, Bh, Kp, bm, bn, 0,  As,        Bs,        tid);
    gemm3_stage(A, Bh, Kp, bm, bn, 32, As + PST3, Bs + PST3, tid);

    int buf = 0;
    for (int s = 0; s < nst; s++) {
        if (s + 1 < nst)
            asm volatile("cp.async.wait_group 1;" ::: "memory");
        else
            asm volatile("cp.async.wait_group 0;" ::: "memory");
        __syncthreads();

        if (s + 2 < nst) {
            int nb = buf + 2; if (nb >= 3) nb -= 3;
            gemm3_stage(A, Bh, Kp, bm, bn, (s + 2) * 32,
                        As + nb * PST3, Bs + nb * PST3, tid);
        }

        const uint32_t* Ab = As + buf * PST3;
        const uint32_t* Bb = Bs + buf * PST3;
        const uint32_t aBase = sm_addr(Ab + (wm + lA_row) * GSTR3 + lA_col);
        const uint32_t bBase = sm_addr(Bb + (wn + lB_row) * GSTR3 + lB_col);

#pragma unroll
        for (int ks = 0; ks < 4; ks++) {
            const uint32_t ko = ks * 32;      // 8 uint32 = 32 bytes
            uint32_t ta[4][4];
#pragma unroll
            for (int mt = 0; mt < 4; mt++)
                ldsm4(ta[mt][0], ta[mt][1], ta[mt][2], ta[mt][3],
                      aBase + mt * 16 * GSTR3 * 4 + ko);
            uint32_t tb[4][2];
#pragma unroll
            for (int np = 0; np < 2; np++)
                ldsm4(tb[2*np][0], tb[2*np][1], tb[2*np+1][0], tb[2*np+1][1],
                      bBase + np * 16 * GSTR3 * 4 + ko);
#pragma unroll
            for (int mt = 0; mt < 4; mt++) {
#pragma unroll
                for (int nt = 0; nt < 4; nt++) {
                    mma_f16(acc[mt][nt],
                            ta[mt][0], ta[mt][1], ta[mt][2], ta[mt][3],
                            tb[nt][0], tb[nt][1]);
                }
            }
        }
        if (++buf == 3) buf = 0;
    }

#pragma unroll
    for (int mt = 0; mt < 4; mt++) {
#pragma unroll
        for (int nt = 0; nt < 4; nt++) {
            const int row0 = bm + wm + mt * 16 + g;
            const int col  = bn + wn + nt * 8 + 2 * tg;
            *(float2*)&C[(size_t)row0 * N + col] =
                make_float2(acc[mt][nt][0], acc[mt][nt][1]);
            *(float2*)&C[(size_t)(row0 + 8) * N + col] =
                make_float2(acc[mt][nt][2], acc[mt][nt][3]);
        }
    }
}

// ---------------------------------------------------------------------------
// KV-cache conversion body (t < P).
// ---------------------------------------------------------------------------
__device__ __forceinline__ void prep_cache_body(
    const float* __restrict__ cache_k, const float* __restrict__ cache_v,
    int t0, int kv, int b, char* smraw)
{
    float (*Vs)[68] = (float(*)[68])smraw;
    const int tid = threadIdx.x;
    const int row = tid >> 2, q = tid & 3;
    const int t = t0 + row;

    {
        const float* src = cache_k + ((size_t)(b * KV_ + kv) * CTX_ + t) * HD_ + q * 16;
        uint32_t* dst = g_K16 + ((size_t)(b * KV_ + kv) * CTX_ + t) * 32 + q * 8;
#pragma unroll
        for (int i = 0; i < 4; i++) {
            float4 f = ((const float4*)src)[i];
            dst[2 * i + 0] = h2pack(f.x, f.y);
            dst[2 * i + 1] = h2pack(f.z, f.w);
        }
    }

    const float* vsrc = cache_v + ((size_t)(b * KV_ + kv) * CTX_ + t) * HD_;
#pragma unroll
    for (int i = 0; i < 4; i++)
        *(float4*)&Vs[row][q * 16 + 4 * i] = ((const float4*)(vsrc + q * 16))[i];
    __syncthreads();

    const int hd = tid >> 2, c = tid & 3;
    uint32_t* vdst = g_Vt16 + ((size_t)(b * KV_ + kv) * HD_ + hd) * (CTX_ / 2)
                   + t0 / 2 + c * 8;
#pragma unroll
    for (int i = 0; i < 8; i++) {
        const int tp = c * 8 + i;
        vdst[i] = h2pack(Vs[2 * tp][hd], Vs[2 * tp + 1][hd]);
    }
}

// ---------------------------------------------------------------------------
// Fused Q+K+V projection + KV-cache prep tail. 640 blocks.
// ---------------------------------------------------------------------------
__global__ __launch_bounds__(256, 2) void gemm_qkv_prep(
    const float* __restrict__ cache_k, const float* __restrict__ cache_v)
{
    extern __shared__ char smraw[];
    const int bid = blockIdx.x;
    if (bid < 384) {
        const int bx = bid % 24, bm = (bid / 24) * 128;
        if (bx < 16)
            gemm3_core(g_X16, g_Wq16, g_Q, E_, E_, bm, bx * 128, smraw);
        else if (bx < 20)
            gemm3_core(g_X16, g_Wk16, g_K, KV_ * HD_, E_, bm, (bx - 16) * 128, smraw);
        else
            gemm3_core(g_X16, g_Wv16, g_V, KV_ * HD_, E_, bm, (bx - 20) * 128, smraw);
    } else {
        const int pb = bid - 384;
        const int t0 = (pb % 16) * 64;
        const int kv = (pb / 16) % 8;
        const int b  = pb / 128;
        prep_cache_body(cache_k, cache_v, t0, kv, b, smraw);
    }
}

__global__ __launch_bounds__(256, 2) void gemm_o(float* __restrict__ out)
{
    extern __shared__ char smraw[];
    gemm3_core(g_A16, g_Wo16, out, E_, E_, blockIdx.y * 128, blockIdx.x * 128, smraw);
}

// ---------------------------------------------------------------------------
// rope_prep: RoPE+convert (Q pre-scaled by log2e/8, new K) + new-V transpose.
// ---------------------------------------------------------------------------
__global__ __launch_bounds__(256) void rope_prep(
    const float* __restrict__ cosp, const float* __restrict__ sinp)
{
    __shared__ float Vs[64][68];
    const int bid = blockIdx.x;
    if (bid < 5120) {
        const int idx = bid * 256 + threadIdx.x;
        constexpr int NH = H_ + KV_;                 // 40
        const int p    = idx & 15;
        const int item = idx >> 4;
        const int hh   = item % NH;
        const int row  = item / NH;                  // b*S + s

        const float* cb = cosp + (size_t)row * HD_;
        const float* sb = sinp + (size_t)row * HD_;
        float c1a = cb[2*p],      c1b = cb[2*p+1];
        float s1a = sb[2*p],      s1b = sb[2*p+1];
        float c2a = cb[2*p+32],   c2b = cb[2*p+33];
        float s2a = sb[2*p+32],   s2b = sb[2*p+33];

        const float* base;
        uint32_t* dst;
        if (hh < H_) {
            base = g_Q + (size_t)row * E_ + hh * HD_;
            dst  = g_Q16 + ((size_t)row * H_ + hh) * 32;
            // fold softmax scale (1/8) and log2(e) into Q
            const float SC = 0.125f * 1.4426950408889634f;
            c1a *= SC; c1b *= SC; s1a *= SC; s1b *= SC;
            c2a *= SC; c2b *= SC; s2a *= SC; s2b *= SC;
        } else {
            const int kvh = hh - H_;
            base = g_K + (size_t)row * (KV_ * HD_) + kvh * HD_;
            const int b = row / S_, s = row % S_;
            dst  = g_K16 + ((size_t)(b * KV_ + kvh) * CTX_ + P_ + s) * 32;
        }
        const float t1a = base[2*p],    t1b = base[2*p+1];
        const float t2a = base[2*p+32], t2b = base[2*p+33];
        dst[p]      = h2pack(t1a * c1a - t2a * s1a, t1b * c1b - t2b * s1b);
        dst[p + 16] = h2pack(t2a * c2a + t1a * s2a, t2b * c2b + t1b * s2b);
    } else {
        const int pb = bid - 5120;                 // 0..255
        const int t0 = P_ + (pb % 16) * 64;
        const int kv = (pb / 16) % 8;
        const int b  = pb / 128;
        const int tid = threadIdx.x;
        const int row = tid >> 2, q = tid & 3;
        const int t = t0 + row;

        const float* vsrc = g_V + (size_t)(b * S_ + (t - P_)) * (KV_ * HD_) + kv * HD_;
#pragma unroll
        for (int i = 0; i < 4; i++)
            *(float4*)&Vs[row][q * 16 + 4 * i] = ((const float4*)(vsrc + q * 16))[i];
        __syncthreads();

        const int hd = tid >> 2, c = tid & 3;
        uint32_t* vdst = g_Vt16 + ((size_t)(b * KV_ + kv) * HD_ + hd) * (CTX_ / 2)
                       + t0 / 2 + c * 8;
#pragma unroll
        for (int i = 0; i < 8; i++) {
            const int tp = c * 8 + i;
            vdst[i] = h2pack(Vs[2 * tp][hd], Vs[2 * tp + 1][hd]);
        }
    }
}

// ---------------------------------------------------------------------------
// Flash attention: BLOCK_M=64, BLOCK_N=128 supertiles, exp2-domain softmax.
// 128 threads (4 warps), ldmatrix frags, double-buffered cp.async.
// ---------------------------------------------------------------------------
constexpr int KTS  = 128 * 36;              // uint32 per K supertile
constexpr int VTS  = 64 * 68;               // uint32 per V supertile
constexpr int ATTN_SMEM = (2 * KTS + 2 * VTS) * 4;   // 71680 B

__global__ __launch_bounds__(128, 3) void attn_mma()
{
    extern __shared__ uint32_t dsm[];
    uint32_t* KsS[2] = { dsm,           dsm + KTS };
    uint32_t* VtS[2] = { dsm + 2 * KTS, dsm + 2 * KTS + VTS };

    // longest blocks (largest m0) first
    const int mblk = (int)gridDim.x - 1 - (int)blockIdx.x;
    const int m0 = mblk * 64;
    const int h  = blockIdx.y;
    const int b  = blockIdx.z;
    const int kv = h / G_;
    const int tid  = threadIdx.x;
    const int warp = tid >> 5;
    const int lane = tid & 31;
    const int g    = lane >> 2;
    const int tg   = lane & 3;

    const int lB_row = (lane & 7) + ((lane >> 4) & 1) * 8;
    const int lB_col = ((lane >> 3) & 1) * 4;

    const uint32_t* kplane = g_K16 + (size_t)(b * KV_ + kv) * CTX_ * 32;
    const uint32_t* vplane = g_Vt16 + (size_t)(b * KV_ + kv) * HD_ * (CTX_ / 2);
    const int ntile = (P_ + m0 + 64 + 127) >> 7;   // 128-key supertiles

    {
#pragma unroll
        for (int i = 0; i < 8; i++) {
            const int sg = tid + i * 128;
            const int kr = sg >> 3, ko = (sg & 7) * 4;
            cp16(KsS[0] + kr * 36 + ko, kplane + (size_t)kr * 32 + ko);
            const int vr = sg >> 4, vo = (sg & 15) * 4;
            cp16(VtS[0] + vr * 68 + vo, vplane + (size_t)vr * (CTX_ / 2) + vo);
        }
        asm volatile("cp.async.commit_group;");
    }

    // Q fragments (pre-scaled fp16 plane), persist across tiles
    uint32_t qf[4][4];
    {
        const uint32_t* q0 = g_Q16 + ((size_t)(b * S_ + m0 + warp * 16 + g)     * H_ + h) * 32;
        const uint32_t* q8 = g_Q16 + ((size_t)(b * S_ + m0 + warp * 16 + g + 8) * H_ + h) * 32;
#pragma unroll
        for (int ks = 0; ks < 4; ks++) {
            qf[ks][0] = q0[tg + 8 * ks];
            qf[ks][1] = q8[tg + 8 * ks];
            qf[ks][2] = q0[tg + 4 + 8 * ks];
            qf[ks][3] = q8[tg + 4 + 8 * ks];
        }
    }

    float o[8][4];
#pragma unroll
    for (int nt = 0; nt < 8; nt++)
#pragma unroll
        for (int r = 0; r < 4; r++) o[nt][r] = 0.f;
    float m0s = -1e30f, m1s = -1e30f, l0 = 0.f, l1 = 0.f;

    const int qpos0 = P_ + m0 + warp * 16 + g;
    const int wmax  = P_ + m0 + warp * 16 + 15;

    for (int it = 0; it < ntile; ++it) {
        const int t0 = it * 128;
        const int buf = it & 1;

        if (it + 1 < ntile) {
            const int nb = (it + 1) & 1;
#pragma unroll
            for (int i = 0; i < 8; i++) {
                const int sg = tid + i * 128;
                const int kr = sg >> 3, ko = (sg & 7) * 4;
                cp16(KsS[nb] + kr * 36 + ko,
                     kplane + (size_t)(t0 + 128 + kr) * 32 + ko);
                const int vr = sg >> 4, vo = (sg & 15) * 4;
                cp16(VtS[nb] + vr * 68 + vo,
                     vplane + (size_t)vr * (CTX_ / 2) + (t0 + 128) / 2 + vo);
            }
            asm volatile("cp.async.commit_group;");
            asm volatile("cp.async.wait_group 1;");
        } else {
            asm volatile("cp.async.wait_group 0;");
        }
        __syncthreads();

        if (t0 <= wmax) {
            const uint32_t kBase = sm_addr(KsS[buf] + lB_row * 36 + lB_col);
            const uint32_t vBase = sm_addr(VtS[buf] + lB_row * 68 + lB_col);

            // --- scores (log2 domain; scale folded into Q) ---
            float s[16][4];
#pragma unroll
            for (int nt = 0; nt < 16; nt++)
#pragma unroll
                for (int r = 0; r < 4; r++) s[nt][r] = 0.f;

#pragma unroll
            for (int ks = 0; ks < 4; ks++) {
#pragma unroll
                for (int np = 0; np < 8; np++) {
                    uint32_t b0, b1, b2, b3;
                    ldsm4(b0, b1, b2, b3,
                          kBase + (np * 16 * 36 + ks * 8) * 4);
                    mma_f16(s[2*np],   qf[ks][0], qf[ks][1], qf[ks][2], qf[ks][3], b0, b1);
                    mma_f16(s[2*np+1], qf[ks][0], qf[ks][1], qf[ks][2], qf[ks][3], b2, b3);
                }
            }

            // --- causal mask ---
            const bool need_mask = (t0 + 127 > P_ + m0 + warp * 16);
            if (need_mask) {
#pragma unroll
                for (int nt = 0; nt < 16; nt++) {
                    const int col = t0 + 8 * nt + 2 * tg;
#pragma unroll
                    for (int r = 0; r < 4; r++) {
                        const int c  = col + (r & 1);
                        const int qp = (r < 2) ? qpos0 : qpos0 + 8;
                        if (c > qp) s[nt][r] = -1e30f;
                    }
                }
            }

            // --- online softmax (exp2 domain, once per 128 keys) ---
            float mx0 = -1e30f, mx1 = -1e30f;
#pragma unroll
            for (int nt = 0; nt < 16; nt++) {
                mx0 = fmaxf(mx0, fmaxf(s[nt][0], s[nt][1]));
                mx1 = fmaxf(mx1, fmaxf(s[nt][2], s[nt][3]));
            }
            mx0 = fmaxf(mx0, __shfl_xor_sync(0xffffffffu, mx0, 1));
            mx0 = fmaxf(mx0, __shfl_xor_sync(0xffffffffu, mx0, 2));
            mx1 = fmaxf(mx1, __shfl_xor_sync(0xffffffffu, mx1, 1));
            mx1 = fmaxf(mx1, __shfl_xor_sync(0xffffffffu, mx1, 2));

            const float mn0 = fmaxf(m0s, mx0);
            const float mn1 = fmaxf(m1s, mx1);
            const float alpha0 = ex2(m0s - mn0);
            const float alpha1 = ex2(m1s - mn1);
            m0s = mn0; m1s = mn1;

            float sum0 = 0.f, sum1 = 0.f;
#pragma unroll
            for (int nt = 0; nt < 16; nt++) {
                s[nt][0] = ex2(s[nt][0] - mn0);
                s[nt][1] = ex2(s[nt][1] - mn0);
                s[nt][2] = ex2(s[nt][2] - mn1);
                s[nt][3] = ex2(s[nt][3] - mn1);
                sum0 += s[nt][0] + s[nt][1];
                sum1 += s[nt][2] + s[nt][3];
            }
            sum0 += __shfl_xor_sync(0xffffffffu, sum0, 1);
            sum0 += __shfl_xor_sync(0xffffffffu, sum0, 2);
            sum1 += __shfl_xor_sync(0xffffffffu, sum1, 1);
            sum1 += __shfl_xor_sync(0xffffffffu, sum1, 2);
            l0 = l0 * alpha0 + sum0;
            l1 = l1 * alpha1 + sum1;

#pragma unroll
            for (int nt = 0; nt < 8; nt++) {
                o[nt][0] *= alpha0; o[nt][1] *= alpha0;
                o[nt][2] *= alpha1; o[nt][3] *= alpha1;
            }

            // --- O += P V over 128 keys (8 k-steps) ---
#pragma unroll
            for (int ks = 0; ks < 8; ks++) {
                uint32_t a0 = h2pack(s[2 * ks][0],     s[2 * ks][1]);
                uint32_t a1 = h2pack(s[2 * ks][2],     s[2 * ks][3]);
                uint32_t a2 = h2pack(s[2 * ks + 1][0], s[2 * ks + 1][1]);
                uint32_t a3 = h2pack(s[2 * ks + 1][2], s[2 * ks + 1][3]);
#pragma unroll
                for (int np = 0; np < 4; np++) {
                    uint32_t b0, b1, b2, b3;
                    ldsm4(b0, b1, b2, b3,
                          vBase + (np * 16 * 68 + ks * 8) * 4);
                    mma_f16(o[2*np],   a0, a1, a2, a3, b0, b1);
                    mma_f16(o[2*np+1], a0, a1, a2, a3, b2, b3);
                }
            }
        }

        __syncthreads();
    }

    // --- epilogue: write fp16 plane for the O projection ---
    const float inv0 = 1.f / l0;
    const float inv1 = 1.f / l1;
    const size_t row0  = (size_t)(b * S_ + m0 + warp * 16 + g);
    const size_t base0 = row0 * (E_ / 2) + h * (HD_ / 2) + tg;
    const size_t base8 = base0 + 4 * E_;
#pragma unroll
    for (int nt = 0; nt < 8; nt++) {
        g_A16[base0 + 4 * nt] = h2pack(o[nt][0] * inv0, o[nt][1] * inv0);
        g_A16[base8 + 4 * nt] = h2pack(o[nt][2] * inv1, o[nt][3] * inv1);
    }
}

// ---------------------------------------------------------------------------
// Launcher
// ---------------------------------------------------------------------------
extern "C" void kernel_launch(void* const* d_in, const int* in_sizes, int n_in,
                              void* d_out, int out_size)
{
    const float* x       = (const float*)d_in[0];
    const float* cosp    = (const float*)d_in[1];
    const float* sinp    = (const float*)d_in[2];
    // d_in[3] = mask (causal; computed analytically)
    const float* cache_k = (const float*)d_in[4];
    const float* cache_v = (const float*)d_in[5];
    const float* Wq      = (const float*)d_in[6];
    const float* Wk      = (const float*)d_in[7];
    const float* Wv      = (const float*)d_in[8];
    const float* Wo      = (const float*)d_in[9];
    float* out           = (float*)d_out;

    cudaFuncSetAttribute(gemm_qkv_prep, cudaFuncAttributeMaxDynamicSharedMemorySize, GSM3);
    cudaFuncSetAttribute(gemm_o,        cudaFuncAttributeMaxDynamicSharedMemorySize, GSM3);
    cudaFuncSetAttribute(attn_mma,      cudaFuncAttributeMaxDynamicSharedMemorySize, ATTN_SMEM);

    // 0) fp16 planes: x + weights (one launch)
    prep_all<<<dim3(M_ * E_ / 2 / 256, 5), 256>>>(x, Wq, Wk, Wv, Wo);

    // 1) fused Q/K/V projections + KV-cache conversion in the wave tail
    gemm_qkv_prep<<<640, 256, GSM3>>>(cache_k, cache_v);

    // 2) RoPE (+scale fold on Q) + new-K convert + new-V transpose
    rope_prep<<<5376, 256>>>(cosp, sinp);

    // 3) flash attention (fp16 mma, exp2 softmax, BLOCK_N=128 supertiles)
    attn_mma<<<dim3(S_ / 64, H_, B_), 128, ATTN_SMEM>>>();

    // 4) output projection (BK=64 pipeline)
    gemm_o<<<dim3(16, 16), 256, GSM3>>>(out);
}

// round 16
// speedup vs baseline: 1.0637x; 1.0637x over previous
#include <cuda_runtime.h>
#include <cuda_fp16.h>
#include <math.h>
#include <stdint.h>

// ---------------------------------------------------------------------------
// Problem constants (LlamaAttention: B=2,S=1024,P=1024,E=2048,H=32,KV=8,HD=64)
// ---------------------------------------------------------------------------
constexpr int B_   = 2;
constexpr int S_   = 1024;
constexpr int P_   = 1024;
constexpr int E_   = 2048;
constexpr int H_   = 32;
constexpr int KV_  = 8;
constexpr int HD_  = 64;
constexpr int G_   = H_ / KV_;        // 4
constexpr int CTX_ = P_ + S_;         // 2048
constexpr int M_   = B_ * S_;         // 2048 rows of tokens

// ---------------------------------------------------------------------------
// Scratch (static device allocations are the sanctioned workaround)
// ---------------------------------------------------------------------------
__device__ float    g_Q[(size_t)M_ * E_];                   // fp32 Q (pre-rope)
__device__ float    g_K[(size_t)M_ * KV_ * HD_];            // fp32 new K (pre-rope)
__device__ float    g_V[(size_t)M_ * KV_ * HD_];            // fp32 new V
__device__ uint32_t g_X16[(size_t)M_ * E_ / 2];             // x fp16 plane
__device__ uint32_t g_A16[(size_t)M_ * E_ / 2];             // attn out fp16 plane
__device__ uint32_t g_Wq16[(size_t)E_ * E_ / 2];            // fp16 packed weights
__device__ uint32_t g_Wk16[(size_t)KV_ * HD_ * E_ / 2];
__device__ uint32_t g_Wv16[(size_t)KV_ * HD_ * E_ / 2];
__device__ uint32_t g_Wo16[(size_t)E_ * E_ / 2];
__device__ uint32_t g_Q16[(size_t)M_ * H_ * 32];            // Q fp16 (pre-scaled by log2e/8)
__device__ uint32_t g_K16[(size_t)B_ * KV_ * CTX_ * 32];    // K fp16 [b][kv][t][hd/2]
__device__ uint32_t g_Vt16[(size_t)B_ * KV_ * HD_ * (CTX_/2)]; // V^T fp16 [b][kv][hd][t/2]

// ---------------------------------------------------------------------------
// helpers
// ---------------------------------------------------------------------------
__device__ __forceinline__ uint32_t h2pack(float a, float b)
{
    __half2 h = __floats2half2_rn(a, b);
    return *reinterpret_cast<uint32_t*>(&h);
}

__device__ __forceinline__ float ex2(float x)
{
    float y;
    asm("ex2.approx.f32 %0, %1;" : "=f"(y) : "f"(x));
    return y;
}

__device__ __forceinline__ uint32_t hex2(uint32_t h)
{
    uint32_t y;
    asm("ex2.approx.f16x2 %0, %1;" : "=r"(y) : "r"(h));
    return y;
}

__device__ __forceinline__ void mma_f16(float c[4],
    uint32_t a0, uint32_t a1, uint32_t a2, uint32_t a3,
    uint32_t b0, uint32_t b1)
{
    asm volatile(
        "mma.sync.aligned.m16n8k16.row.col.f32.f16.f16.f32 "
        "{%0,%1,%2,%3}, {%4,%5,%6,%7}, {%8,%9}, {%0,%1,%2,%3};"
        : "+f"(c[0]), "+f"(c[1]), "+f"(c[2]), "+f"(c[3])
        : "r"(a0), "r"(a1), "r"(a2), "r"(a3), "r"(b0), "r"(b1));
}

__device__ __forceinline__ void cp16(void* smem_dst, const void* gsrc)
{
    uint32_t d = (uint32_t)__cvta_generic_to_shared(smem_dst);
    asm volatile("cp.async.cg.shared.global [%0], [%1], 16;" :: "r"(d), "l"(gsrc));
}

__device__ __forceinline__ uint32_t sm_addr(const void* p)
{
    return (uint32_t)__cvta_generic_to_shared(p);
}

__device__ __forceinline__ void ldsm4(uint32_t& r0, uint32_t& r1,
                                      uint32_t& r2, uint32_t& r3, uint32_t addr)
{
    asm volatile("ldmatrix.sync.aligned.m8n8.x4.shared.b16 {%0,%1,%2,%3}, [%4];"
                 : "=r"(r0), "=r"(r1), "=r"(r2), "=r"(r3) : "r"(addr));
}

// ---------------------------------------------------------------------------
// prep_all: single launch converting x and all weights to fp16 planes.
// ---------------------------------------------------------------------------
__global__ void prep_all(const float* __restrict__ x,
                         const float* __restrict__ Wq, const float* __restrict__ Wk,
                         const float* __restrict__ Wv, const float* __restrict__ Wo)
{
    const int i = blockIdx.x * blockDim.x + threadIdx.x;
    const int y = blockIdx.y;
    if (y == 0) {
        float2 f = *(const float2*)(x + 2 * i);
        g_X16[i] = h2pack(f.x, f.y);
    } else if (y == 1) {
        float2 f = *(const float2*)(Wq + 2 * i);
        g_Wq16[i] = h2pack(f.x, f.y);
    } else if (y == 2) {
        if (i < KV_ * HD_ * E_ / 2) {
            float2 f = *(const float2*)(Wk + 2 * i);
            g_Wk16[i] = h2pack(f.x, f.y);
        }
    } else if (y == 3) {
        if (i < KV_ * HD_ * E_ / 2) {
            float2 f = *(const float2*)(Wv + 2 * i);
            g_Wv16[i] = h2pack(f.x, f.y);
        }
    } else {
        float2 f = *(const float2*)(Wo + 2 * i);
        g_Wo16[i] = h2pack(f.x, f.y);
    }
}

// ---------------------------------------------------------------------------
// Plain fp16 GEMM core, BK=32 (reverted: the known-best configuration).
// 128x128 tile, 256 threads, 8 warps (2x4), warp tile 64x32.
// 3-stage cp.async pipeline, ONE __syncthreads per stage, ldmatrix frags.
// ---------------------------------------------------------------------------
constexpr int GSTR2 = 20;             // plane stride in uint32 (16 used + 4 pad)
constexpr int PST   = 128 * GSTR2;    // uint32 per plane stage (10240 B)
constexpr int GSM2  = 3 * 2 * PST * 4;   // 61440 B

__device__ __forceinline__ void gemm2_stage(
    const uint32_t* __restrict__ A, const uint32_t* __restrict__ Bh,
    int Kp, int bm, int bn, int kp0, uint32_t* Ad, uint32_t* Bd, int tid)
{
#pragma unroll
    for (int i = 0; i < 2; i++) {
        int c = tid * 2 + i;
        int row = c >> 2, off = (c & 3) * 4;
        cp16(Ad + row * GSTR2 + off, A  + (size_t)(bm + row) * Kp + kp0 + off);
        cp16(Bd + row * GSTR2 + off, Bh + (size_t)(bn + row) * Kp + kp0 + off);
    }
    asm volatile("cp.async.commit_group;" ::: "memory");
}

__device__ __forceinline__ void gemm2_core(
    const uint32_t* __restrict__ A, const uint32_t* __restrict__ Bh,
    float* __restrict__ C, int N, int K, int bm, int bn, char* smraw)
{
    uint32_t* As = (uint32_t*)smraw;
    uint32_t* Bs = (uint32_t*)(smraw + 3 * PST * 4);
    const int tid  = threadIdx.x;
    const int warp = tid >> 5;
    const int lane = tid & 31;
    const int g    = lane >> 2;
    const int tg   = lane & 3;
    const int wm   = (warp >> 2) * 64;
    const int wn   = (warp & 3) * 32;
    const int Kp   = K / 2;

    const int lA_row = (lane & 7) + ((lane >> 3) & 1) * 8;
    const int lA_col = ((lane >> 4) & 1) * 4;
    const int lB_row = (lane & 7) + ((lane >> 4) & 1) * 8;
    const int lB_col = ((lane >> 3) & 1) * 4;

    float acc[4][4][4];
#pragma unroll
    for (int i = 0; i < 4; i++)
#pragma unroll
        for (int j = 0; j < 4; j++)
#pragma unroll
            for (int r = 0; r < 4; r++) acc[i][j][r] = 0.f;

    const int nst = K / 32;
    gemm2_stage(A, Bh, Kp, bm, bn, 0,  As,       Bs,       tid);
    gemm2_stage(A, Bh, Kp, bm, bn, 16, As + PST, Bs + PST, tid);

    int buf = 0;
    for (int s = 0; s < nst; s++) {
        if (s + 1 < nst)
            asm volatile("cp.async.wait_group 1;" ::: "memory");
        else
            asm volatile("cp.async.wait_group 0;" ::: "memory");
        __syncthreads();

        if (s + 2 < nst) {
            int nb = buf + 2; if (nb >= 3) nb -= 3;
            gemm2_stage(A, Bh, Kp, bm, bn, (s + 2) * 16,
                        As + nb * PST, Bs + nb * PST, tid);
        }

        const uint32_t* Ab = As + buf * PST;
        const uint32_t* Bb = Bs + buf * PST;
        const uint32_t aBase = sm_addr(Ab + (wm + lA_row) * GSTR2 + lA_col);
        const uint32_t bBase = sm_addr(Bb + (wn + lB_row) * GSTR2 + lB_col);

#pragma unroll
        for (int ks = 0; ks < 2; ks++) {
            const uint32_t ko = ks * 32;
            uint32_t ta[4][4];
#pragma unroll
            for (int mt = 0; mt < 4; mt++)
                ldsm4(ta[mt][0], ta[mt][1], ta[mt][2], ta[mt][3],
                      aBase + mt * 16 * GSTR2 * 4 + ko);
            uint32_t tb[4][2];
#pragma unroll
            for (int np = 0; np < 2; np++)
                ldsm4(tb[2*np][0], tb[2*np][1], tb[2*np+1][0], tb[2*np+1][1],
                      bBase + np * 16 * GSTR2 * 4 + ko);
#pragma unroll
            for (int mt = 0; mt < 4; mt++) {
#pragma unroll
                for (int nt = 0; nt < 4; nt++) {
                    mma_f16(acc[mt][nt],
                            ta[mt][0], ta[mt][1], ta[mt][2], ta[mt][3],
                            tb[nt][0], tb[nt][1]);
                }
            }
        }
        if (++buf == 3) buf = 0;
    }

#pragma unroll
    for (int mt = 0; mt < 4; mt++) {
#pragma unroll
        for (int nt = 0; nt < 4; nt++) {
            const int row0 = bm + wm + mt * 16 + g;
            const int col  = bn + wn + nt * 8 + 2 * tg;
            *(float2*)&C[(size_t)row0 * N + col] =
                make_float2(acc[mt][nt][0], acc[mt][nt][1]);
            *(float2*)&C[(size_t)(row0 + 8) * N + col] =
                make_float2(acc[mt][nt][2], acc[mt][nt][3]);
        }
    }
}

// ---------------------------------------------------------------------------
// KV-cache conversion body (t < P).
// ---------------------------------------------------------------------------
__device__ __forceinline__ void prep_cache_body(
    const float* __restrict__ cache_k, const float* __restrict__ cache_v,
    int t0, int kv, int b, char* smraw)
{
    float (*Vs)[68] = (float(*)[68])smraw;
    const int tid = threadIdx.x;
    const int row = tid >> 2, q = tid & 3;
    const int t = t0 + row;

    {
        const float* src = cache_k + ((size_t)(b * KV_ + kv) * CTX_ + t) * HD_ + q * 16;
        uint32_t* dst = g_K16 + ((size_t)(b * KV_ + kv) * CTX_ + t) * 32 + q * 8;
#pragma unroll
        for (int i = 0; i < 4; i++) {
            float4 f = ((const float4*)src)[i];
            dst[2 * i + 0] = h2pack(f.x, f.y);
            dst[2 * i + 1] = h2pack(f.z, f.w);
        }
    }

    const float* vsrc = cache_v + ((size_t)(b * KV_ + kv) * CTX_ + t) * HD_;
#pragma unroll
    for (int i = 0; i < 4; i++)
        *(float4*)&Vs[row][q * 16 + 4 * i] = ((const float4*)(vsrc + q * 16))[i];
    __syncthreads();

    const int hd = tid >> 2, c = tid & 3;
    uint32_t* vdst = g_Vt16 + ((size_t)(b * KV_ + kv) * HD_ + hd) * (CTX_ / 2)
                   + t0 / 2 + c * 8;
#pragma unroll
    for (int i = 0; i < 8; i++) {
        const int tp = c * 8 + i;
        vdst[i] = h2pack(Vs[2 * tp][hd], Vs[2 * tp + 1][hd]);
    }
}

// ---------------------------------------------------------------------------
// Fused Q+K+V projection + KV-cache prep tail. 640 blocks.
// ---------------------------------------------------------------------------
__global__ __launch_bounds__(256, 2) void gemm_qkv_prep(
    const float* __restrict__ cache_k, const float* __restrict__ cache_v)
{
    extern __shared__ char smraw[];
    const int bid = blockIdx.x;
    if (bid < 384) {
        const int bx = bid % 24, bm = (bid / 24) * 128;
        if (bx < 16)
            gemm2_core(g_X16, g_Wq16, g_Q, E_, E_, bm, bx * 128, smraw);
        else if (bx < 20)
            gemm2_core(g_X16, g_Wk16, g_K, KV_ * HD_, E_, bm, (bx - 16) * 128, smraw);
        else
            gemm2_core(g_X16, g_Wv16, g_V, KV_ * HD_, E_, bm, (bx - 20) * 128, smraw);
    } else {
        const int pb = bid - 384;
        const int t0 = (pb % 16) * 64;
        const int kv = (pb / 16) % 8;
        const int b  = pb / 128;
        prep_cache_body(cache_k, cache_v, t0, kv, b, smraw);
    }
}

__global__ __launch_bounds__(256, 2) void gemm_o(float* __restrict__ out)
{
    extern __shared__ char smraw[];
    gemm2_core(g_A16, g_Wo16, out, E_, E_, blockIdx.y * 128, blockIdx.x * 128, smraw);
}

// ---------------------------------------------------------------------------
// rope_prep: RoPE+convert (Q pre-scaled by log2e/8, new K) + new-V transpose.
// ---------------------------------------------------------------------------
__global__ __launch_bounds__(256) void rope_prep(
    const float* __restrict__ cosp, const float* __restrict__ sinp)
{
    __shared__ float Vs[64][68];
    const int bid = blockIdx.x;
    if (bid < 5120) {
        const int idx = bid * 256 + threadIdx.x;
        constexpr int NH = H_ + KV_;                 // 40
        const int p    = idx & 15;
        const int item = idx >> 4;
        const int hh   = item % NH;
        const int row  = item / NH;                  // b*S + s

        const float* cb = cosp + (size_t)row * HD_;
        const float* sb = sinp + (size_t)row * HD_;
        float c1a = cb[2*p],      c1b = cb[2*p+1];
        float s1a = sb[2*p],      s1b = sb[2*p+1];
        float c2a = cb[2*p+32],   c2b = cb[2*p+33];
        float s2a = sb[2*p+32],   s2b = sb[2*p+33];

        const float* base;
        uint32_t* dst;
        if (hh < H_) {
            base = g_Q + (size_t)row * E_ + hh * HD_;
            dst  = g_Q16 + ((size_t)row * H_ + hh) * 32;
            // fold softmax scale (1/8) and log2(e) into Q
            const float SC = 0.125f * 1.4426950408889634f;
            c1a *= SC; c1b *= SC; s1a *= SC; s1b *= SC;
            c2a *= SC; c2b *= SC; s2a *= SC; s2b *= SC;
        } else {
            const int kvh = hh - H_;
            base = g_K + (size_t)row * (KV_ * HD_) + kvh * HD_;
            const int b = row / S_, s = row % S_;
            dst  = g_K16 + ((size_t)(b * KV_ + kvh) * CTX_ + P_ + s) * 32;
        }
        const float t1a = base[2*p],    t1b = base[2*p+1];
        const float t2a = base[2*p+32], t2b = base[2*p+33];
        dst[p]      = h2pack(t1a * c1a - t2a * s1a, t1b * c1b - t2b * s1b);
        dst[p + 16] = h2pack(t2a * c2a + t1a * s2a, t2b * c2b + t1b * s2b);
    } else {
        const int pb = bid - 5120;                 // 0..255
        const int t0 = P_ + (pb % 16) * 64;
        const int kv = (pb / 16) % 8;
        const int b  = pb / 128;
        const int tid = threadIdx.x;
        const int row = tid >> 2, q = tid & 3;
        const int t = t0 + row;

        const float* vsrc = g_V + (size_t)(b * S_ + (t - P_)) * (KV_ * HD_) + kv * HD_;
#pragma unroll
        for (int i = 0; i < 4; i++)
            *(float4*)&Vs[row][q * 16 + 4 * i] = ((const float4*)(vsrc + q * 16))[i];
        __syncthreads();

        const int hd = tid >> 2, c = tid & 3;
        uint32_t* vdst = g_Vt16 + ((size_t)(b * KV_ + kv) * HD_ + hd) * (CTX_ / 2)
                       + t0 / 2 + c * 8;
#pragma unroll
        for (int i = 0; i < 8; i++) {
            const int tp = c * 8 + i;
            vdst[i] = h2pack(Vs[2 * tp][hd], Vs[2 * tp + 1][hd]);
        }
    }
}

// ---------------------------------------------------------------------------
// Flash attention: BLOCK_M=64, BLOCK_N=128 supertiles, f16x2-exp2 softmax.
// 128 threads (4 warps), ldmatrix frags, double-buffered cp.async.
// ---------------------------------------------------------------------------
constexpr int KTS  = 128 * 36;              // uint32 per K supertile
constexpr int VTS  = 64 * 68;               // uint32 per V supertile
constexpr int ATTN_SMEM = (2 * KTS + 2 * VTS) * 4;   // 71680 B

__global__ __launch_bounds__(128, 3) void attn_mma()
{
    extern __shared__ uint32_t dsm[];
    uint32_t* KsS[2] = { dsm,           dsm + KTS };
    uint32_t* VtS[2] = { dsm + 2 * KTS, dsm + 2 * KTS + VTS };

    // longest blocks (largest m0) first
    const int mblk = (int)gridDim.x - 1 - (int)blockIdx.x;
    const int m0 = mblk * 64;
    const int h  = blockIdx.y;
    const int b  = blockIdx.z;
    const int kv = h / G_;
    const int tid  = threadIdx.x;
    const int warp = tid >> 5;
    const int lane = tid & 31;
    const int g    = lane >> 2;
    const int tg   = lane & 3;

    const int lB_row = (lane & 7) + ((lane >> 4) & 1) * 8;
    const int lB_col = ((lane >> 3) & 1) * 4;

    const uint32_t* kplane = g_K16 + (size_t)(b * KV_ + kv) * CTX_ * 32;
    const uint32_t* vplane = g_Vt16 + (size_t)(b * KV_ + kv) * HD_ * (CTX_ / 2);
    const int ntile = (P_ + m0 + 64 + 127) >> 7;   // 128-key supertiles

    {
#pragma unroll
        for (int i = 0; i < 8; i++) {
            const int sg = tid + i * 128;
            const int kr = sg >> 3, ko = (sg & 7) * 4;
            cp16(KsS[0] + kr * 36 + ko, kplane + (size_t)kr * 32 + ko);
            const int vr = sg >> 4, vo = (sg & 15) * 4;
            cp16(VtS[0] + vr * 68 + vo, vplane + (size_t)vr * (CTX_ / 2) + vo);
        }
        asm volatile("cp.async.commit_group;");
    }

    // Q fragments (pre-scaled fp16 plane), persist across tiles
    uint32_t qf[4][4];
    {
        const uint32_t* q0 = g_Q16 + ((size_t)(b * S_ + m0 + warp * 16 + g)     * H_ + h) * 32;
        const uint32_t* q8 = g_Q16 + ((size_t)(b * S_ + m0 + warp * 16 + g + 8) * H_ + h) * 32;
#pragma unroll
        for (int ks = 0; ks < 4; ks++) {
            qf[ks][0] = q0[tg + 8 * ks];
            qf[ks][1] = q8[tg + 8 * ks];
            qf[ks][2] = q0[tg + 4 + 8 * ks];
            qf[ks][3] = q8[tg + 4 + 8 * ks];
        }
    }

    float o[8][4];
#pragma unroll
    for (int nt = 0; nt < 8; nt++)
#pragma unroll
        for (int r = 0; r < 4; r++) o[nt][r] = 0.f;
    float m0s = -1e30f, m1s = -1e30f, l0 = 0.f, l1 = 0.f;

    const int qpos0 = P_ + m0 + warp * 16 + g;
    const int wmax  = P_ + m0 + warp * 16 + 15;

    for (int it = 0; it < ntile; ++it) {
        const int t0 = it * 128;
        const int buf = it & 1;

        if (it + 1 < ntile) {
            const int nb = (it + 1) & 1;
#pragma unroll
            for (int i = 0; i < 8; i++) {
                const int sg = tid + i * 128;
                const int kr = sg >> 3, ko = (sg & 7) * 4;
                cp16(KsS[nb] + kr * 36 + ko,
                     kplane + (size_t)(t0 + 128 + kr) * 32 + ko);
                const int vr = sg >> 4, vo = (sg & 15) * 4;
                cp16(VtS[nb] + vr * 68 + vo,
                     vplane + (size_t)vr * (CTX_ / 2) + (t0 + 128) / 2 + vo);
            }
            asm volatile("cp.async.commit_group;");
            asm volatile("cp.async.wait_group 1;");
        } else {
            asm volatile("cp.async.wait_group 0;");
        }
        __syncthreads();

        if (t0 <= wmax) {
            const uint32_t kBase = sm_addr(KsS[buf] + lB_row * 36 + lB_col);
            const uint32_t vBase = sm_addr(VtS[buf] + lB_row * 68 + lB_col);

            // --- scores (log2 domain; scale folded into Q) ---
            float s[16][4];
#pragma unroll
            for (int nt = 0; nt < 16; nt++)
#pragma unroll
                for (int r = 0; r < 4; r++) s[nt][r] = 0.f;

#pragma unroll
            for (int ks = 0; ks < 4; ks++) {
#pragma unroll
                for (int np = 0; np < 8; np++) {
                    uint32_t b0, b1, b2, b3;
                    ldsm4(b0, b1, b2, b3,
                          kBase + (np * 16 * 36 + ks * 8) * 4);
                    mma_f16(s[2*np],   qf[ks][0], qf[ks][1], qf[ks][2], qf[ks][3], b0, b1);
                    mma_f16(s[2*np+1], qf[ks][0], qf[ks][1], qf[ks][2], qf[ks][3], b2, b3);
                }
            }

            // --- causal mask ---
            const bool need_mask = (t0 + 127 > P_ + m0 + warp * 16);
            if (need_mask) {
#pragma unroll
                for (int nt = 0; nt < 16; nt++) {
                    const int col = t0 + 8 * nt + 2 * tg;
#pragma unroll
                    for (int r = 0; r < 4; r++) {
                        const int c  = col + (r & 1);
                        const int qp = (r < 2) ? qpos0 : qpos0 + 8;
                        if (c > qp) s[nt][r] = -1e30f;
                    }
                }
            }

            // --- online softmax: max reduce ---
            float mx0 = -1e30f, mx1 = -1e30f;
#pragma unroll
            for (int nt = 0; nt < 16; nt++) {
                mx0 = fmaxf(mx0, fmaxf(s[nt][0], s[nt][1]));
                mx1 = fmaxf(mx1, fmaxf(s[nt][2], s[nt][3]));
            }
            mx0 = fmaxf(mx0, __shfl_xor_sync(0xffffffffu, mx0, 1));
            mx0 = fmaxf(mx0, __shfl_xor_sync(0xffffffffu, mx0, 2));
            mx1 = fmaxf(mx1, __shfl_xor_sync(0xffffffffu, mx1, 1));
            mx1 = fmaxf(mx1, __shfl_xor_sync(0xffffffffu, mx1, 2));

            const float mn0 = fmaxf(m0s, mx0);
            const float mn1 = fmaxf(m1s, mx1);
            const float alpha0 = ex2(m0s - mn0);
            const float alpha1 = ex2(m1s - mn1);
            m0s = mn0; m1s = mn1;

            // --- P = exp2(s - mn) via f16x2 MUFU; P fragments ready for PV ---
            uint32_t ph0[16], ph1[16];
            float sum0 = 0.f, sum1 = 0.f;
#pragma unroll
            for (int nt = 0; nt < 16; nt++) {
                ph0[nt] = hex2(h2pack(s[nt][0] - mn0, s[nt][1] - mn0));
                ph1[nt] = hex2(h2pack(s[nt][2] - mn1, s[nt][3] - mn1));
                float2 f0 = __half22float2(*reinterpret_cast<__half2*>(&ph0[nt]));
                float2 f1 = __half22float2(*reinterpret_cast<__half2*>(&ph1[nt]));
                sum0 += f0.x + f0.y;
                sum1 += f1.x + f1.y;
            }
            sum0 += __shfl_xor_sync(0xffffffffu, sum0, 1);
            sum0 += __shfl_xor_sync(0xffffffffu, sum0, 2);
            sum1 += __shfl_xor_sync(0xffffffffu, sum1, 1);
            sum1 += __shfl_xor_sync(0xffffffffu, sum1, 2);
            l0 = l0 * alpha0 + sum0;
            l1 = l1 * alpha1 + sum1;

#pragma unroll
            for (int nt = 0; nt < 8; nt++) {
                o[nt][0] *= alpha0; o[nt][1] *= alpha0;
                o[nt][2] *= alpha1; o[nt][3] *= alpha1;
            }

            // --- O += P V over 128 keys (8 k-steps) ---
#pragma unroll
            for (int ks = 0; ks < 8; ks++) {
                const uint32_t a0 = ph0[2 * ks];
                const uint32_t a1 = ph1[2 * ks];
                const uint32_t a2 = ph0[2 * ks + 1];
                const uint32_t a3 = ph1[2 * ks + 1];
#pragma unroll
                for (int np = 0; np < 4; np++) {
                    uint32_t b0, b1, b2, b3;
                    ldsm4(b0, b1, b2, b3,
                          vBase + (np * 16 * 68 + ks * 8) * 4);
                    mma_f16(o[2*np],   a0, a1, a2, a3, b0, b1);
                    mma_f16(o[2*np+1], a0, a1, a2, a3, b2, b3);
                }
            }
        }

        __syncthreads();
    }

    // --- epilogue: write fp16 plane for the O projection ---
    const float inv0 = 1.f / l0;
    const float inv1 = 1.f / l1;
    const size_t row0  = (size_t)(b * S_ + m0 + warp * 16 + g);
    const size_t base0 = row0 * (E_ / 2) + h * (HD_ / 2) + tg;
    const size_t base8 = base0 + 4 * E_;
#pragma unroll
    for (int nt = 0; nt < 8; nt++) {
        g_A16[base0 + 4 * nt] = h2pack(o[nt][0] * inv0, o[nt][1] * inv0);
        g_A16[base8 + 4 * nt] = h2pack(o[nt][2] * inv1, o[nt][3] * inv1);
    }
}

// ---------------------------------------------------------------------------
// Launcher
// ---------------------------------------------------------------------------
extern "C" void kernel_launch(void* const* d_in, const int* in_sizes, int n_in,
                              void* d_out, int out_size)
{
    const float* x       = (const float*)d_in[0];
    const float* cosp    = (const float*)d_in[1];
    const float* sinp    = (const float*)d_in[2];
    // d_in[3] = mask (causal; computed analytically)
    const float* cache_k = (const float*)d_in[4];
    const float* cache_v = (const float*)d_in[5];
    const float* Wq      = (const float*)d_in[6];
    const float* Wk      = (const float*)d_in[7];
    const float* Wv      = (const float*)d_in[8];
    const float* Wo      = (const float*)d_in[9];
    float* out           = (float*)d_out;

    cudaFuncSetAttribute(gemm_qkv_prep, cudaFuncAttributeMaxDynamicSharedMemorySize, GSM2);
    cudaFuncSetAttribute(gemm_o,        cudaFuncAttributeMaxDynamicSharedMemorySize, GSM2);
    cudaFuncSetAttribute(attn_mma,      cudaFuncAttributeMaxDynamicSharedMemorySize, ATTN_SMEM);

    // 0) fp16 planes: x + weights (one launch)
    prep_all<<<dim3(M_ * E_ / 2 / 256, 5), 256>>>(x, Wq, Wk, Wv, Wo);

    // 1) fused Q/K/V projections + KV-cache conversion in the wave tail
    gemm_qkv_prep<<<640, 256, GSM2>>>(cache_k, cache_v);

    // 2) RoPE (+scale fold on Q) + new-K convert + new-V transpose
    rope_prep<<<5376, 256>>>(cosp, sinp);

    // 3) flash attention (fp16 mma, f16x2 exp2 softmax, BLOCK_N=128)
    attn_mma<<<dim3(S_ / 64, H_, B_), 128, ATTN_SMEM>>>();

    // 4) output projection (BK=32 pipeline)
    gemm_o<<<dim3(16, 16), 256, GSM2>>>(out);
}

// round 17
// speedup vs baseline: 1.0744x; 1.0101x over previous
#include <cuda_runtime.h>
#include <cuda_fp16.h>
#include <math.h>
#include <stdint.h>

// ---------------------------------------------------------------------------
// Problem constants (LlamaAttention: B=2,S=1024,P=1024,E=2048,H=32,KV=8,HD=64)
// ---------------------------------------------------------------------------
constexpr int B_   = 2;
constexpr int S_   = 1024;
constexpr int P_   = 1024;
constexpr int E_   = 2048;
constexpr int H_   = 32;
constexpr int KV_  = 8;
constexpr int HD_  = 64;
constexpr int G_   = H_ / KV_;        // 4
constexpr int CTX_ = P_ + S_;         // 2048
constexpr int M_   = B_ * S_;         // 2048 rows of tokens

// ---------------------------------------------------------------------------
// Scratch (static device allocations are the sanctioned workaround)
// ---------------------------------------------------------------------------
__device__ float    g_Q[(size_t)M_ * E_];                   // fp32 Q (pre-rope)
__device__ float    g_K[(size_t)M_ * KV_ * HD_];            // fp32 new K (pre-rope)
__device__ float    g_V[(size_t)M_ * KV_ * HD_];            // fp32 new V
__device__ uint32_t g_X16[(size_t)M_ * E_ / 2];             // x fp16 plane
__device__ uint32_t g_A16[(size_t)M_ * E_ / 2];             // attn out fp16 plane
__device__ uint32_t g_Wq16[(size_t)E_ * E_ / 2];            // fp16 packed weights
__device__ uint32_t g_Wk16[(size_t)KV_ * HD_ * E_ / 2];
__device__ uint32_t g_Wv16[(size_t)KV_ * HD_ * E_ / 2];
__device__ uint32_t g_Wo16[(size_t)E_ * E_ / 2];
__device__ uint32_t g_Q16[(size_t)M_ * H_ * 32];            // Q fp16 (pre-scaled by log2e/8)
__device__ uint32_t g_K16[(size_t)B_ * KV_ * CTX_ * 32];    // K fp16 [b][kv][t][hd/2]
__device__ uint32_t g_Vt16[(size_t)B_ * KV_ * HD_ * (CTX_/2)]; // V^T fp16 [b][kv][hd][t/2]

// ---------------------------------------------------------------------------
// helpers
// ---------------------------------------------------------------------------
__device__ __forceinline__ uint32_t h2pack(float a, float b)
{
    __half2 h = __floats2half2_rn(a, b);
    return *reinterpret_cast<uint32_t*>(&h);
}

__device__ __forceinline__ float ex2(float x)
{
    float y;
    asm("ex2.approx.f32 %0, %1;" : "=f"(y) : "f"(x));
    return y;
}

__device__ __forceinline__ uint32_t hex2(uint32_t h)
{
    uint32_t y;
    asm("ex2.approx.f16x2 %0, %1;" : "=r"(y) : "r"(h));
    return y;
}

__device__ __forceinline__ void mma_f16(float c[4],
    uint32_t a0, uint32_t a1, uint32_t a2, uint32_t a3,
    uint32_t b0, uint32_t b1)
{
    asm volatile(
        "mma.sync.aligned.m16n8k16.row.col.f32.f16.f16.f32 "
        "{%0,%1,%2,%3}, {%4,%5,%6,%7}, {%8,%9}, {%0,%1,%2,%3};"
        : "+f"(c[0]), "+f"(c[1]), "+f"(c[2]), "+f"(c[3])
        : "r"(a0), "r"(a1), "r"(a2), "r"(a3), "r"(b0), "r"(b1));
}

__device__ __forceinline__ void cp16(void* smem_dst, const void* gsrc)
{
    uint32_t d = (uint32_t)__cvta_generic_to_shared(smem_dst);
    asm volatile("cp.async.cg.shared.global [%0], [%1], 16;" :: "r"(d), "l"(gsrc));
}

__device__ __forceinline__ uint32_t sm_addr(const void* p)
{
    return (uint32_t)__cvta_generic_to_shared(p);
}

__device__ __forceinline__ void ldsm4(uint32_t& r0, uint32_t& r1,
                                      uint32_t& r2, uint32_t& r3, uint32_t addr)
{
    asm volatile("ldmatrix.sync.aligned.m8n8.x4.shared.b16 {%0,%1,%2,%3}, [%4];"
                 : "=r"(r0), "=r"(r1), "=r"(r2), "=r"(r3) : "r"(addr));
}

// ---------------------------------------------------------------------------
// prep_all: single launch converting x and all weights to fp16 planes.
// ---------------------------------------------------------------------------
__global__ void prep_all(const float* __restrict__ x,
                         const float* __restrict__ Wq, const float* __restrict__ Wk,
                         const float* __restrict__ Wv, const float* __restrict__ Wo)
{
    const int i = blockIdx.x * blockDim.x + threadIdx.x;
    const int y = blockIdx.y;
    if (y == 0) {
        float2 f = *(const float2*)(x + 2 * i);
        g_X16[i] = h2pack(f.x, f.y);
    } else if (y == 1) {
        float2 f = *(const float2*)(Wq + 2 * i);
        g_Wq16[i] = h2pack(f.x, f.y);
    } else if (y == 2) {
        if (i < KV_ * HD_ * E_ / 2) {
            float2 f = *(const float2*)(Wk + 2 * i);
            g_Wk16[i] = h2pack(f.x, f.y);
        }
    } else if (y == 3) {
        if (i < KV_ * HD_ * E_ / 2) {
            float2 f = *(const float2*)(Wv + 2 * i);
            g_Wv16[i] = h2pack(f.x, f.y);
        }
    } else {
        float2 f = *(const float2*)(Wo + 2 * i);
        g_Wo16[i] = h2pack(f.x, f.y);
    }
}

// ---------------------------------------------------------------------------
// Plain fp16 GEMM core, BK=32 (known-best configuration).
// 128x128 tile, 256 threads, 8 warps (2x4), warp tile 64x32.
// 3-stage cp.async pipeline, ONE __syncthreads per stage, ldmatrix frags.
// ---------------------------------------------------------------------------
constexpr int GSTR2 = 20;             // plane stride in uint32 (16 used + 4 pad)
constexpr int PST   = 128 * GSTR2;    // uint32 per plane stage (10240 B)
constexpr int GSM2  = 3 * 2 * PST * 4;   // 61440 B

__device__ __forceinline__ void gemm2_stage(
    const uint32_t* __restrict__ A, const uint32_t* __restrict__ Bh,
    int Kp, int bm, int bn, int kp0, uint32_t* Ad, uint32_t* Bd, int tid)
{
#pragma unroll
    for (int i = 0; i < 2; i++) {
        int c = tid * 2 + i;
        int row = c >> 2, off = (c & 3) * 4;
        cp16(Ad + row * GSTR2 + off, A  + (size_t)(bm + row) * Kp + kp0 + off);
        cp16(Bd + row * GSTR2 + off, Bh + (size_t)(bn + row) * Kp + kp0 + off);
    }
    asm volatile("cp.async.commit_group;" ::: "memory");
}

__device__ __forceinline__ void gemm2_core(
    const uint32_t* __restrict__ A, const uint32_t* __restrict__ Bh,
    float* __restrict__ C, int N, int K, int bm, int bn, char* smraw)
{
    uint32_t* As = (uint32_t*)smraw;
    uint32_t* Bs = (uint32_t*)(smraw + 3 * PST * 4);
    const int tid  = threadIdx.x;
    const int warp = tid >> 5;
    const int lane = tid & 31;
    const int g    = lane >> 2;
    const int tg   = lane & 3;
    const int wm   = (warp >> 2) * 64;
    const int wn   = (warp & 3) * 32;
    const int Kp   = K / 2;

    const int lA_row = (lane & 7) + ((lane >> 3) & 1) * 8;
    const int lA_col = ((lane >> 4) & 1) * 4;
    const int lB_row = (lane & 7) + ((lane >> 4) & 1) * 8;
    const int lB_col = ((lane >> 3) & 1) * 4;

    float acc[4][4][4];
#pragma unroll
    for (int i = 0; i < 4; i++)
#pragma unroll
        for (int j = 0; j < 4; j++)
#pragma unroll
            for (int r = 0; r < 4; r++) acc[i][j][r] = 0.f;

    const int nst = K / 32;
    gemm2_stage(A, Bh, Kp, bm, bn, 0,  As,       Bs,       tid);
    gemm2_stage(A, Bh, Kp, bm, bn, 16, As + PST, Bs + PST, tid);

    int buf = 0;
    for (int s = 0; s < nst; s++) {
        if (s + 1 < nst)
            asm volatile("cp.async.wait_group 1;" ::: "memory");
        else
            asm volatile("cp.async.wait_group 0;" ::: "memory");
        __syncthreads();

        if (s + 2 < nst) {
            int nb = buf + 2; if (nb >= 3) nb -= 3;
            gemm2_stage(A, Bh, Kp, bm, bn, (s + 2) * 16,
                        As + nb * PST, Bs + nb * PST, tid);
        }

        const uint32_t* Ab = As + buf * PST;
        const uint32_t* Bb = Bs + buf * PST;
        const uint32_t aBase = sm_addr(Ab + (wm + lA_row) * GSTR2 + lA_col);
        const uint32_t bBase = sm_addr(Bb + (wn + lB_row) * GSTR2 + lB_col);

#pragma unroll
        for (int ks = 0; ks < 2; ks++) {
            const uint32_t ko = ks * 32;
            uint32_t ta[4][4];
#pragma unroll
            for (int mt = 0; mt < 4; mt++)
                ldsm4(ta[mt][0], ta[mt][1], ta[mt][2], ta[mt][3],
                      aBase + mt * 16 * GSTR2 * 4 + ko);
            uint32_t tb[4][2];
#pragma unroll
            for (int np = 0; np < 2; np++)
                ldsm4(tb[2*np][0], tb[2*np][1], tb[2*np+1][0], tb[2*np+1][1],
                      bBase + np * 16 * GSTR2 * 4 + ko);
#pragma unroll
            for (int mt = 0; mt < 4; mt++) {
#pragma unroll
                for (int nt = 0; nt < 4; nt++) {
                    mma_f16(acc[mt][nt],
                            ta[mt][0], ta[mt][1], ta[mt][2], ta[mt][3],
                            tb[nt][0], tb[nt][1]);
                }
            }
        }
        if (++buf == 3) buf = 0;
    }

#pragma unroll
    for (int mt = 0; mt < 4; mt++) {
#pragma unroll
        for (int nt = 0; nt < 4; nt++) {
            const int row0 = bm + wm + mt * 16 + g;
            const int col  = bn + wn + nt * 8 + 2 * tg;
            *(float2*)&C[(size_t)row0 * N + col] =
                make_float2(acc[mt][nt][0], acc[mt][nt][1]);
            *(float2*)&C[(size_t)(row0 + 8) * N + col] =
                make_float2(acc[mt][nt][2], acc[mt][nt][3]);
        }
    }
}

// ---------------------------------------------------------------------------
// KV-cache conversion body (t < P).
// ---------------------------------------------------------------------------
__device__ __forceinline__ void prep_cache_body(
    const float* __restrict__ cache_k, const float* __restrict__ cache_v,
    int t0, int kv, int b, char* smraw)
{
    float (*Vs)[68] = (float(*)[68])smraw;
    const int tid = threadIdx.x;
    const int row = tid >> 2, q = tid & 3;
    const int t = t0 + row;

    {
        const float* src = cache_k + ((size_t)(b * KV_ + kv) * CTX_ + t) * HD_ + q * 16;
        uint32_t* dst = g_K16 + ((size_t)(b * KV_ + kv) * CTX_ + t) * 32 + q * 8;
#pragma unroll
        for (int i = 0; i < 4; i++) {
            float4 f = ((const float4*)src)[i];
            dst[2 * i + 0] = h2pack(f.x, f.y);
            dst[2 * i + 1] = h2pack(f.z, f.w);
        }
    }

    const float* vsrc = cache_v + ((size_t)(b * KV_ + kv) * CTX_ + t) * HD_;
#pragma unroll
    for (int i = 0; i < 4; i++)
        *(float4*)&Vs[row][q * 16 + 4 * i] = ((const float4*)(vsrc + q * 16))[i];
    __syncthreads();

    const int hd = tid >> 2, c = tid & 3;
    uint32_t* vdst = g_Vt16 + ((size_t)(b * KV_ + kv) * HD_ + hd) * (CTX_ / 2)
                   + t0 / 2 + c * 8;
#pragma unroll
    for (int i = 0; i < 8; i++) {
        const int tp = c * 8 + i;
        vdst[i] = h2pack(Vs[2 * tp][hd], Vs[2 * tp + 1][hd]);
    }
}

// ---------------------------------------------------------------------------
// Fused Q+K+V projection + KV-cache prep tail. 640 blocks.
// ---------------------------------------------------------------------------
__global__ __launch_bounds__(256, 2) void gemm_qkv_prep(
    const float* __restrict__ cache_k, const float* __restrict__ cache_v)
{
    extern __shared__ char smraw[];
    const int bid = blockIdx.x;
    if (bid < 384) {
        const int bx = bid % 24, bm = (bid / 24) * 128;
        if (bx < 16)
            gemm2_core(g_X16, g_Wq16, g_Q, E_, E_, bm, bx * 128, smraw);
        else if (bx < 20)
            gemm2_core(g_X16, g_Wk16, g_K, KV_ * HD_, E_, bm, (bx - 16) * 128, smraw);
        else
            gemm2_core(g_X16, g_Wv16, g_V, KV_ * HD_, E_, bm, (bx - 20) * 128, smraw);
    } else {
        const int pb = bid - 384;
        const int t0 = (pb % 16) * 64;
        const int kv = (pb / 16) % 8;
        const int b  = pb / 128;
        prep_cache_body(cache_k, cache_v, t0, kv, b, smraw);
    }
}

__global__ __launch_bounds__(256, 2) void gemm_o(float* __restrict__ out)
{
    extern __shared__ char smraw[];
    gemm2_core(g_A16, g_Wo16, out, E_, E_, blockIdx.y * 128, blockIdx.x * 128, smraw);
}

// ---------------------------------------------------------------------------
// rope_prep: RoPE+convert (Q pre-scaled by log2e/8, new K) + new-V transpose.
// ---------------------------------------------------------------------------
__global__ __launch_bounds__(256) void rope_prep(
    const float* __restrict__ cosp, const float* __restrict__ sinp)
{
    __shared__ float Vs[64][68];
    const int bid = blockIdx.x;
    if (bid < 5120) {
        const int idx = bid * 256 + threadIdx.x;
        constexpr int NH = H_ + KV_;                 // 40
        const int p    = idx & 15;
        const int item = idx >> 4;
        const int hh   = item % NH;
        const int row  = item / NH;                  // b*S + s

        const float* cb = cosp + (size_t)row * HD_;
        const float* sb = sinp + (size_t)row * HD_;
        float c1a = cb[2*p],      c1b = cb[2*p+1];
        float s1a = sb[2*p],      s1b = sb[2*p+1];
        float c2a = cb[2*p+32],   c2b = cb[2*p+33];
        float s2a = sb[2*p+32],   s2b = sb[2*p+33];

        const float* base;
        uint32_t* dst;
        if (hh < H_) {
            base = g_Q + (size_t)row * E_ + hh * HD_;
            dst  = g_Q16 + ((size_t)row * H_ + hh) * 32;
            // fold softmax scale (1/8) and log2(e) into Q
            const float SC = 0.125f * 1.4426950408889634f;
            c1a *= SC; c1b *= SC; s1a *= SC; s1b *= SC;
            c2a *= SC; c2b *= SC; s2a *= SC; s2b *= SC;
        } else {
            const int kvh = hh - H_;
            base = g_K + (size_t)row * (KV_ * HD_) + kvh * HD_;
            const int b = row / S_, s = row % S_;
            dst  = g_K16 + ((size_t)(b * KV_ + kvh) * CTX_ + P_ + s) * 32;
        }
        const float t1a = base[2*p],    t1b = base[2*p+1];
        const float t2a = base[2*p+32], t2b = base[2*p+33];
        dst[p]      = h2pack(t1a * c1a - t2a * s1a, t1b * c1b - t2b * s1b);
        dst[p + 16] = h2pack(t2a * c2a + t1a * s2a, t2b * c2b + t1b * s2b);
    } else {
        const int pb = bid - 5120;                 // 0..255
        const int t0 = P_ + (pb % 16) * 64;
        const int kv = (pb / 16) % 8;
        const int b  = pb / 128;
        const int tid = threadIdx.x;
        const int row = tid >> 2, q = tid & 3;
        const int t = t0 + row;

        const float* vsrc = g_V + (size_t)(b * S_ + (t - P_)) * (KV_ * HD_) + kv * HD_;
#pragma unroll
        for (int i = 0; i < 4; i++)
            *(float4*)&Vs[row][q * 16 + 4 * i] = ((const float4*)(vsrc + q * 16))[i];
        __syncthreads();

        const int hd = tid >> 2, c = tid & 3;
        uint32_t* vdst = g_Vt16 + ((size_t)(b * KV_ + kv) * HD_ + hd) * (CTX_ / 2)
                       + t0 / 2 + c * 8;
#pragma unroll
        for (int i = 0; i < 8; i++) {
            const int tp = c * 8 + i;
            vdst[i] = h2pack(Vs[2 * tp][hd], Vs[2 * tp + 1][hd]);
        }
    }
}

// ---------------------------------------------------------------------------
// Flash attention: BLOCK_M=64, BLOCK_N=64, f16x2-exp2 softmax, 4 blocks/SM.
// 128 threads (4 warps), ldmatrix frags, double-buffered cp.async.
// ---------------------------------------------------------------------------
constexpr int KT = 64 * 36;   // uint32 per K or V tile (stride 36, 32 used)

__global__ __launch_bounds__(128, 4) void attn_mma()
{
    __shared__ uint32_t KsS[2][KT];
    __shared__ uint32_t VtS[2][KT];

    // longest blocks (largest m0) first
    const int mblk = (int)gridDim.x - 1 - (int)blockIdx.x;
    const int m0 = mblk * 64;
    const int h  = blockIdx.y;
    const int b  = blockIdx.z;
    const int kv = h / G_;
    const int tid  = threadIdx.x;
    const int warp = tid >> 5;
    const int lane = tid & 31;
    const int g    = lane >> 2;
    const int tg   = lane & 3;

    const int lB_row = (lane & 7) + ((lane >> 4) & 1) * 8;
    const int lB_col = ((lane >> 3) & 1) * 4;

    const uint32_t* kplane = g_K16 + (size_t)(b * KV_ + kv) * CTX_ * 32;
    const uint32_t* vplane = g_Vt16 + (size_t)(b * KV_ + kv) * HD_ * (CTX_ / 2);
    const int ntile = (P_ + m0 + 64) / 64;

    // tile 0 loads: 512 16B-segments per tile over 128 threads (4 each)
    {
#pragma unroll
        for (int i = 0; i < 4; i++) {
            const int sg = tid + i * 128;
            const int row = sg >> 3, off = (sg & 7) * 4;
            cp16(&KsS[0][row * 36 + off], kplane + (size_t)row * 32 + off);
            cp16(&VtS[0][row * 36 + off], vplane + (size_t)row * (CTX_ / 2) + off);
        }
        asm volatile("cp.async.commit_group;");
    }

    // Q fragments (pre-scaled fp16 plane), persist across tiles
    uint32_t qf[4][4];
    {
        const uint32_t* q0 = g_Q16 + ((size_t)(b * S_ + m0 + warp * 16 + g)     * H_ + h) * 32;
        const uint32_t* q8 = g_Q16 + ((size_t)(b * S_ + m0 + warp * 16 + g + 8) * H_ + h) * 32;
#pragma unroll
        for (int ks = 0; ks < 4; ks++) {
            qf[ks][0] = q0[tg + 8 * ks];
            qf[ks][1] = q8[tg + 8 * ks];
            qf[ks][2] = q0[tg + 4 + 8 * ks];
            qf[ks][3] = q8[tg + 4 + 8 * ks];
        }
    }

    float o[8][4];
#pragma unroll
    for (int nt = 0; nt < 8; nt++)
#pragma unroll
        for (int r = 0; r < 4; r++) o[nt][r] = 0.f;
    float m0s = -1e30f, m1s = -1e30f, l0 = 0.f, l1 = 0.f;

    const int qpos0 = P_ + m0 + warp * 16 + g;
    const int wmax  = P_ + m0 + warp * 16 + 15;

    for (int it = 0; it < ntile; ++it) {
        const int t0 = it * 64;
        const int buf = it & 1;

        if (it + 1 < ntile) {
            const int nb = (it + 1) & 1;
#pragma unroll
            for (int i = 0; i < 4; i++) {
                const int sg = tid + i * 128;
                const int row = sg >> 3, off = (sg & 7) * 4;
                cp16(&KsS[nb][row * 36 + off],
                     kplane + (size_t)(t0 + 64 + row) * 32 + off);
                cp16(&VtS[nb][row * 36 + off],
                     vplane + (size_t)row * (CTX_ / 2) + (t0 + 64) / 2 + off);
            }
            asm volatile("cp.async.commit_group;");
            asm volatile("cp.async.wait_group 1;");
        } else {
            asm volatile("cp.async.wait_group 0;");
        }
        __syncthreads();

        if (t0 <= wmax) {
            const uint32_t kBase = sm_addr(&KsS[buf][lB_row * 36 + lB_col]);
            const uint32_t vBase = sm_addr(&VtS[buf][lB_row * 36 + lB_col]);

            // --- scores (log2 domain; scale folded into Q) ---
            float s[8][4];
#pragma unroll
            for (int nt = 0; nt < 8; nt++)
#pragma unroll
                for (int r = 0; r < 4; r++) s[nt][r] = 0.f;

#pragma unroll
            for (int ks = 0; ks < 4; ks++) {
#pragma unroll
                for (int np = 0; np < 4; np++) {
                    uint32_t b0, b1, b2, b3;
                    ldsm4(b0, b1, b2, b3,
                          kBase + (np * 16 * 36 + ks * 8) * 4);
                    mma_f16(s[2*np],   qf[ks][0], qf[ks][1], qf[ks][2], qf[ks][3], b0, b1);
                    mma_f16(s[2*np+1], qf[ks][0], qf[ks][1], qf[ks][2], qf[ks][3], b2, b3);
                }
            }

            // --- causal mask ---
            const bool need_mask = (t0 + 63 > P_ + m0 + warp * 16);
            if (need_mask) {
#pragma unroll
                for (int nt = 0; nt < 8; nt++) {
                    const int col = t0 + 8 * nt + 2 * tg;
#pragma unroll
                    for (int r = 0; r < 4; r++) {
                        const int c  = col + (r & 1);
                        const int qp = (r < 2) ? qpos0 : qpos0 + 8;
                        if (c > qp) s[nt][r] = -1e30f;
                    }
                }
            }

            // --- online softmax: max reduce ---
            float mx0 = -1e30f, mx1 = -1e30f;
#pragma unroll
            for (int nt = 0; nt < 8; nt++) {
                mx0 = fmaxf(mx0, fmaxf(s[nt][0], s[nt][1]));
                mx1 = fmaxf(mx1, fmaxf(s[nt][2], s[nt][3]));
            }
            mx0 = fmaxf(mx0, __shfl_xor_sync(0xffffffffu, mx0, 1));
            mx0 = fmaxf(mx0, __shfl_xor_sync(0xffffffffu, mx0, 2));
            mx1 = fmaxf(mx1, __shfl_xor_sync(0xffffffffu, mx1, 1));
            mx1 = fmaxf(mx1, __shfl_xor_sync(0xffffffffu, mx1, 2));

            const float mn0 = fmaxf(m0s, mx0);
            const float mn1 = fmaxf(m1s, mx1);
            const float alpha0 = ex2(m0s - mn0);
            const float alpha1 = ex2(m1s - mn1);
            m0s = mn0; m1s = mn1;

            // --- P = exp2(s - mn) via f16x2 MUFU; fragments ready for PV ---
            uint32_t ph0[8], ph1[8];
            float sum0 = 0.f, sum1 = 0.f;
#pragma unroll
            for (int nt = 0; nt < 8; nt++) {
                ph0[nt] = hex2(h2pack(s[nt][0] - mn0, s[nt][1] - mn0));
                ph1[nt] = hex2(h2pack(s[nt][2] - mn1, s[nt][3] - mn1));
                float2 f0 = __half22float2(*reinterpret_cast<__half2*>(&ph0[nt]));
                float2 f1 = __half22float2(*reinterpret_cast<__half2*>(&ph1[nt]));
                sum0 += f0.x + f0.y;
                sum1 += f1.x + f1.y;
            }
            sum0 += __shfl_xor_sync(0xffffffffu, sum0, 1);
            sum0 += __shfl_xor_sync(0xffffffffu, sum0, 2);
            sum1 += __shfl_xor_sync(0xffffffffu, sum1, 1);
            sum1 += __shfl_xor_sync(0xffffffffu, sum1, 2);
            l0 = l0 * alpha0 + sum0;
            l1 = l1 * alpha1 + sum1;

#pragma unroll
            for (int nt = 0; nt < 8; nt++) {
                o[nt][0] *= alpha0; o[nt][1] *= alpha0;
                o[nt][2] *= alpha1; o[nt][3] *= alpha1;
            }

            // --- O += P V (4 k-steps) ---
#pragma unroll
            for (int ks = 0; ks < 4; ks++) {
                const uint32_t a0 = ph0[2 * ks];
                const uint32_t a1 = ph1[2 * ks];
                const uint32_t a2 = ph0[2 * ks + 1];
                const uint32_t a3 = ph1[2 * ks + 1];
#pragma unroll
                for (int np = 0; np < 4; np++) {
                    uint32_t b0, b1, b2, b3;
                    ldsm4(b0, b1, b2, b3,
                          vBase + (np * 16 * 36 + ks * 8) * 4);
                    mma_f16(o[2*np],   a0, a1, a2, a3, b0, b1);
                    mma_f16(o[2*np+1], a0, a1, a2, a3, b2, b3);
                }
            }
        }

        __syncthreads();
    }

    // --- epilogue: write fp16 plane for the O projection ---
    const float inv0 = 1.f / l0;
    const float inv1 = 1.f / l1;
    const size_t row0  = (size_t)(b * S_ + m0 + warp * 16 + g);
    const size_t base0 = row0 * (E_ / 2) + h * (HD_ / 2) + tg;
    const size_t base8 = base0 + 4 * E_;
#pragma unroll
    for (int nt = 0; nt < 8; nt++) {
        g_A16[base0 + 4 * nt] = h2pack(o[nt][0] * inv0, o[nt][1] * inv0);
        g_A16[base8 + 4 * nt] = h2pack(o[nt][2] * inv1, o[nt][3] * inv1);
    }
}

// ---------------------------------------------------------------------------
// Launcher
// ---------------------------------------------------------------------------
extern "C" void kernel_launch(void* const* d_in, const int* in_sizes, int n_in,
                              void* d_out, int out_size)
{
    const float* x       = (const float*)d_in[0];
    const float* cosp    = (const float*)d_in[1];
    const float* sinp    = (const float*)d_in[2];
    // d_in[3] = mask (causal; computed analytically)
    const float* cache_k = (const float*)d_in[4];
    const float* cache_v = (const float*)d_in[5];
    const float* Wq      = (const float*)d_in[6];
    const float* Wk      = (const float*)d_in[7];
    const float* Wv      = (const float*)d_in[8];
    const float* Wo      = (const float*)d_in[9];
    float* out           = (float*)d_out;

    cudaFuncSetAttribute(gemm_qkv_prep, cudaFuncAttributeMaxDynamicSharedMemorySize, GSM2);
    cudaFuncSetAttribute(gemm_o,        cudaFuncAttributeMaxDynamicSharedMemorySize, GSM2);

    // 0) fp16 planes: x + weights (one launch)
    prep_all<<<dim3(M_ * E_ / 2 / 256, 5), 256>>>(x, Wq, Wk, Wv, Wo);

    // 1) fused Q/K/V projections + KV-cache conversion in the wave tail
    gemm_qkv_prep<<<640, 256, GSM2>>>(cache_k, cache_v);

    // 2) RoPE (+scale fold on Q) + new-K convert + new-V transpose
    rope_prep<<<5376, 256>>>(cosp, sinp);

    // 3) flash attention (fp16 mma, f16x2 exp2, BLOCK_N=64, 4 blocks/SM)
    attn_mma<<<dim3(S_ / 64, H_, B_), 128>>>();

    // 4) output projection (BK=32 pipeline)
    gemm_o<<<dim3(16, 16), 256, GSM2>>>(out);
}